// round 3
// baseline (speedup 1.0000x reference)
#include <cuda_runtime.h>

// Problem dims (fixed by reference)
#define B 16
#define S 4096
#define D 1024      // D_IN = H = D_OUT = 1024
#define NCHUNK 32
#define SCHUNK (S / NCHUNK)   // 128

// Scratch (no device allocs allowed)
__device__ float g_part[B * NCHUNK * D];   // 2 MB
__device__ float g_m[B * D];
__device__ float g_enc[B * D];

// K1: partial sums over an S-chunk. grid (NCHUNK, B), block 256.
// Each thread owns 4 contiguous floats (one float4 column) of D.
__global__ void reduce_partial_kernel(const float* __restrict__ x,
                                      float* __restrict__ part) {
    const int b = blockIdx.y;
    const int chunk = blockIdx.x;
    const int tid = threadIdx.x;  // 0..255

    const float4* xb = (const float4*)(x + (size_t)b * S * D + (size_t)chunk * SCHUNK * D);

    float4 acc0 = make_float4(0.f, 0.f, 0.f, 0.f);
    float4 acc1 = make_float4(0.f, 0.f, 0.f, 0.f);
    float4 acc2 = make_float4(0.f, 0.f, 0.f, 0.f);
    float4 acc3 = make_float4(0.f, 0.f, 0.f, 0.f);

    // SCHUNK = 128 rows, 4 independent accumulators -> MLP 4, no FADD chain bind
    #pragma unroll 4
    for (int s = 0; s < SCHUNK; s += 4) {
        float4 v0 = xb[(size_t)(s + 0) * (D / 4) + tid];
        float4 v1 = xb[(size_t)(s + 1) * (D / 4) + tid];
        float4 v2 = xb[(size_t)(s + 2) * (D / 4) + tid];
        float4 v3 = xb[(size_t)(s + 3) * (D / 4) + tid];
        acc0.x += v0.x; acc0.y += v0.y; acc0.z += v0.z; acc0.w += v0.w;
        acc1.x += v1.x; acc1.y += v1.y; acc1.z += v1.z; acc1.w += v1.w;
        acc2.x += v2.x; acc2.y += v2.y; acc2.z += v2.z; acc2.w += v2.w;
        acc3.x += v3.x; acc3.y += v3.y; acc3.z += v3.z; acc3.w += v3.w;
    }

    float4 acc;
    acc.x = (acc0.x + acc1.x) + (acc2.x + acc3.x);
    acc.y = (acc0.y + acc1.y) + (acc2.y + acc3.y);
    acc.z = (acc0.z + acc1.z) + (acc2.z + acc3.z);
    acc.w = (acc0.w + acc1.w) + (acc2.w + acc3.w);

    float4* p = (float4*)(part + ((size_t)b * NCHUNK + chunk) * D);
    p[tid] = acc;
}

// K2: combine NCHUNK partials, apply 1/S. One thread per (b,d).
__global__ void combine_kernel(const float* __restrict__ part,
                               float* __restrict__ m) {
    const int i = blockIdx.x * blockDim.x + threadIdx.x;  // 0 .. B*D-1
    if (i >= B * D) return;
    const int b = i >> 10;
    const int d = i & (D - 1);
    float s = 0.f;
    #pragma unroll
    for (int c = 0; c < NCHUNK; c++)
        s += part[((size_t)b * NCHUNK + c) * D + d];
    m[i] = s * (1.0f / (float)S);
}

// K3/K4: vout[b][n] = dot(vin[b], W[n]) + bias[n].
// grid (N/8, B), block 256 (8 warps, warp-per-output). vin row cached in smem.
__global__ void gemv_kernel(const float* __restrict__ vin,   // [B, K]
                            const float* __restrict__ W,     // [N, K]
                            const float* __restrict__ bias,  // [N]
                            float* __restrict__ vout) {      // [B, N]
    const int K = D;
    __shared__ float sh[D];

    const int b = blockIdx.y;
    for (int i = threadIdx.x; i < K / 4; i += 256)
        ((float4*)sh)[i] = ((const float4*)(vin + (size_t)b * K))[i];
    __syncthreads();

    const int warp = threadIdx.x >> 5;
    const int lane = threadIdx.x & 31;
    const int n = blockIdx.x * 8 + warp;

    const float4* Wr = (const float4*)(W + (size_t)n * K);
    const float4* mv = (const float4*)sh;

    float acc = 0.f;
    #pragma unroll
    for (int i = lane; i < K / 4; i += 32) {   // 8 iterations
        float4 w = Wr[i];
        float4 v = mv[i];
        acc += w.x * v.x + w.y * v.y + w.z * v.z + w.w * v.w;
    }
    #pragma unroll
    for (int o = 16; o; o >>= 1)
        acc += __shfl_xor_sync(0xFFFFFFFFu, acc, o);

    if (lane == 0)
        vout[(size_t)b * D + n] = acc + bias[n];
}

extern "C" void kernel_launch(void* const* d_in, const int* in_sizes, int n_in,
                              void* d_out, int out_size) {
    const float* x     = (const float*)d_in[0];
    const float* W_enc = (const float*)d_in[1];
    const float* b_enc = (const float*)d_in[2];
    const float* W_out = (const float*)d_in[3];
    const float* b_out = (const float*)d_in[4];
    float* out = (float*)d_out;

    float* part; cudaGetSymbolAddress((void**)&part, g_part);
    float* m;    cudaGetSymbolAddress((void**)&m,    g_m);
    float* enc;  cudaGetSymbolAddress((void**)&enc,  g_enc);

    reduce_partial_kernel<<<dim3(NCHUNK, B), 256>>>(x, part);
    combine_kernel<<<(B * D + 255) / 256, 256>>>(part, m);
    gemv_kernel<<<dim3(D / 8, B), 256>>>(m,   W_enc, b_enc, enc);
    gemv_kernel<<<dim3(D / 8, B), 256>>>(enc, W_out, b_out, out);
}